// round 2
// baseline (speedup 1.0000x reference)
#include <cuda_runtime.h>
#include <cstdint>

#define B_N 262144
#define C_N 256
#define D_N 64
#define O_N 8

#define THREADS 256
#define TILE_ROWS 128
#define TR 4            // rows per thread
#define TC 8            // clusters per thread per chunk
#define CCHUNK 64       // clusters per chunk (8 tx groups * TC)
#define XS 68           // x tile row stride in floats (bank-conflict padding)
#define CS 68           // centers row stride in floats

// shared memory layout (floats)
#define SX_OFF   0
#define SC_OFF   (SX_OFF + TILE_ROWS * XS)          // 8704
#define SW_OFF   (SC_OFF + C_N * CS)                // +17408
#define S2_OFF   (SW_OFF + C_N * 8)                 // +2048
#define K2_OFF   (S2_OFF + C_N)                     // +256
#define PD_OFF   (K2_OFF + C_N)                     // +256
#define PN_OFF   (PD_OFF + 8 * TILE_ROWS)           // +1024
#define SMEM_FLOATS (PN_OFF + 8 * TILE_ROWS * 9)    // +9216 => 38912 floats = 152 KB

__device__ __forceinline__ unsigned long long ffma2(unsigned long long a,
                                                    unsigned long long b,
                                                    unsigned long long c) {
    unsigned long long d;
    asm("fma.rn.f32x2 %0, %1, %2, %3;" : "=l"(d) : "l"(a), "l"(b), "l"(c));
    return d;
}

__device__ __forceinline__ float2 unpack2(unsigned long long v) {
    float2 r;
    asm("mov.b64 {%0, %1}, %2;" : "=f"(r.x), "=f"(r.y) : "l"(v));
    return r;
}

__device__ __forceinline__ unsigned long long pack2(float a) {
    unsigned long long r;
    asm("mov.b64 %0, {%1, %2};" : "=l"(r) : "f"(a), "f"(a));
    return r;
}

__device__ __forceinline__ float ex2f(float x) {
    float r;
    asm("ex2.approx.f32 %0, %1;" : "=f"(r) : "f"(x));
    return r;
}

__global__ void __launch_bounds__(THREADS, 1)
fuzzy_kernel(const float* __restrict__ x,
             const float* __restrict__ centers,
             const float* __restrict__ widths,
             const float* __restrict__ rw,
             float* __restrict__ out) {
    extern __shared__ __align__(16) float smem[];
    float* sx   = smem + SX_OFF;
    float* sc   = smem + SC_OFF;
    float* sw   = smem + SW_OFF;
    float* s2c  = smem + S2_OFF;
    float* k2n  = smem + K2_OFF;
    float* pden = smem + PD_OFF;
    float* pnum = smem + PN_OFF;

    const int tid = threadIdx.x;
    const int tx = tid & 7;       // cluster subgroup 0..7
    const int ty = tid >> 3;      // row group 0..31
    const int rowbase = blockIdx.x * TILE_ROWS;

    // ---- cooperative loads into SMEM ----
    // centers: 256x64 = 4096 float4
    {
        const float4* g = reinterpret_cast<const float4*>(centers);
#pragma unroll
        for (int i = 0; i < 16; i++) {
            int idx = tid + i * 256;
            int r = idx >> 4, d4 = idx & 15;
            float4 v = g[idx];
            *reinterpret_cast<float4*>(&sc[r * CS + d4 * 4]) = v;
        }
    }
    // x tile: 128x64 = 2048 float4
    {
        const float4* g = reinterpret_cast<const float4*>(x + (size_t)rowbase * D_N);
#pragma unroll
        for (int i = 0; i < 8; i++) {
            int idx = tid + i * 256;
            int r = idx >> 4, d4 = idx & 15;
            float4 v = g[idx];
            *reinterpret_cast<float4*>(&sx[r * XS + d4 * 4]) = v;
        }
    }
    // rule weights: 256x8 = 512 float4
    {
        const float4* g = reinterpret_cast<const float4*>(rw);
        float4* s = reinterpret_cast<float4*>(sw);
        s[tid] = g[tid];
        s[tid + 256] = g[tid + 256];
    }
    __syncthreads();

    // ---- per-cluster constants: s2 = log2e/(2 w^2), k2n = -||c||^2 * s2 ----
    {
        float csq = 0.f;
#pragma unroll
        for (int d4 = 0; d4 < 16; d4++) {
            float4 v = *reinterpret_cast<const float4*>(&sc[tid * CS + d4 * 4]);
            csq = fmaf(v.x, v.x, csq);
            csq = fmaf(v.y, v.y, csq);
            csq = fmaf(v.z, v.z, csq);
            csq = fmaf(v.w, v.w, csq);
        }
        float w = widths[tid];
        const float LOG2E = 1.4426950408889634f;
        float s = LOG2E / (2.f * w * w);
        s2c[tid] = s;
        k2n[tid] = -csq * s;
    }

    // ---- x_sq for this thread's TR rows ----
    float xsq[TR];
#pragma unroll
    for (int r = 0; r < TR; r++) {
        int row = ty * TR + r;
        float a = 0.f;
#pragma unroll
        for (int d4 = 0; d4 < 16; d4++) {
            float4 v = *reinterpret_cast<const float4*>(&sx[row * XS + d4 * 4]);
            a = fmaf(v.x, v.x, a);
            a = fmaf(v.y, v.y, a);
            a = fmaf(v.z, v.z, a);
            a = fmaf(v.w, v.w, a);
        }
        xsq[r] = a;
    }
    __syncthreads();   // s2c/k2n visible to all

    // ---- accumulators for normalization + output ----
    float den[TR];
    unsigned long long num2[TR][4];
#pragma unroll
    for (int r = 0; r < TR; r++) {
        den[r] = 0.f;
#pragma unroll
        for (int k = 0; k < 4; k++) num2[r][k] = 0ull;
    }

    // ---- chunked cluster loop ----
    for (int c0 = 0; c0 < C_N; c0 += CCHUNK) {
        const int cb = c0 + tx * TC;

        unsigned long long acc[TR][TC];
#pragma unroll
        for (int r = 0; r < TR; r++)
#pragma unroll
            for (int j = 0; j < TC; j++) acc[r][j] = 0ull;

#pragma unroll 4
        for (int d4 = 0; d4 < 16; d4++) {
            ulonglong2 xv[TR];
#pragma unroll
            for (int r = 0; r < TR; r++)
                xv[r] = *reinterpret_cast<const ulonglong2*>(
                    &sx[(ty * TR + r) * XS + d4 * 4]);
#pragma unroll
            for (int j = 0; j < TC; j++) {
                ulonglong2 cv = *reinterpret_cast<const ulonglong2*>(
                    &sc[(cb + j) * CS + d4 * 4]);
#pragma unroll
                for (int r = 0; r < TR; r++) {
                    acc[r][j] = ffma2(xv[r].x, cv.x, acc[r][j]);
                    acc[r][j] = ffma2(xv[r].y, cv.y, acc[r][j]);
                }
            }
        }

        // epilogue: memb + accumulate den / num
#pragma unroll
        for (int j = 0; j < TC; j++) {
            int c = cb + j;
            float s2 = s2c[c];
            float kk = k2n[c];
            ulonglong2 wv0 = *reinterpret_cast<const ulonglong2*>(&sw[c * 8]);
            ulonglong2 wv1 = *reinterpret_cast<const ulonglong2*>(&sw[c * 8 + 4]);
#pragma unroll
            for (int r = 0; r < TR; r++) {
                float2 u = unpack2(acc[r][j]);
                float cross = u.x + u.y;
                float t = fmaf(cross, 2.0f, -xsq[r]);      // 2*cross - ||x||^2
                float lg = fmaf(s2, t, kk);                 // log2(memb)
                float m = ex2f(lg);
                den[r] += m;
                unsigned long long mm = pack2(m);
                num2[r][0] = ffma2(mm, wv0.x, num2[r][0]);
                num2[r][1] = ffma2(mm, wv0.y, num2[r][1]);
                num2[r][2] = ffma2(mm, wv1.x, num2[r][2]);
                num2[r][3] = ffma2(mm, wv1.y, num2[r][3]);
            }
        }
    }

    // ---- deterministic cross-tx reduction via SMEM ----
#pragma unroll
    for (int r = 0; r < TR; r++) {
        int row = ty * TR + r;
        pden[tx * TILE_ROWS + row] = den[r];
        float* pn = &pnum[(tx * TILE_ROWS + row) * 9];
#pragma unroll
        for (int k = 0; k < 4; k++) {
            float2 u = unpack2(num2[r][k]);
            pn[2 * k]     = u.x;
            pn[2 * k + 1] = u.y;
        }
    }
    __syncthreads();

    if (tid < TILE_ROWS) {
        int row = tid;
        float d = 0.f;
#pragma unroll
        for (int t = 0; t < 8; t++) d += pden[t * TILE_ROWS + row];
        float inv = 1.0f / d;
        float o[8];
#pragma unroll
        for (int k = 0; k < 8; k++) o[k] = 0.f;
#pragma unroll
        for (int t = 0; t < 8; t++) {
            const float* pn = &pnum[(t * TILE_ROWS + row) * 9];
#pragma unroll
            for (int k = 0; k < 8; k++) o[k] += pn[k];
        }
        float4* go = reinterpret_cast<float4*>(out + (size_t)(rowbase + row) * 8);
        go[0] = make_float4(o[0] * inv, o[1] * inv, o[2] * inv, o[3] * inv);
        go[1] = make_float4(o[4] * inv, o[5] * inv, o[6] * inv, o[7] * inv);
    }
}

extern "C" void kernel_launch(void* const* d_in, const int* in_sizes, int n_in,
                              void* d_out, int out_size) {
    const float* x       = (const float*)d_in[0];
    const float* centers = (const float*)d_in[1];
    const float* widths  = (const float*)d_in[2];
    const float* rw      = (const float*)d_in[3];
    float* out = (float*)d_out;

    size_t smem_bytes = (size_t)SMEM_FLOATS * sizeof(float);   // 155648 B
    cudaFuncSetAttribute(fuzzy_kernel,
                         cudaFuncAttributeMaxDynamicSharedMemorySize,
                         (int)smem_bytes);
    fuzzy_kernel<<<B_N / TILE_ROWS, THREADS, smem_bytes>>>(x, centers, widths, rw, out);
}

// round 3
// speedup vs baseline: 4.2955x; 4.2955x over previous
#include <cuda_runtime.h>
#include <cstdint>

#define B_N 262144
#define C_N 256
#define D_N 64
#define O_N 8

#define THREADS 128
#define TILE_ROWS 64
#define GRID (B_N / TILE_ROWS)      // 4096
#define TR 4                         // rows per thread (ty 0..15)
#define TC 8                         // clusters per thread per inner chunk
#define CHALF 128                    // clusters resident per outer chunk

// shared memory layout (floats). Rows are exactly 64 floats; conflicts are
// avoided with an XOR swizzle on the float4 index: d4' = d4 ^ (row & 7).
#define SX_OFF 0                                  // 64 rows  * 64 = 4096
#define SC_OFF (SX_OFF + TILE_ROWS * 64)          // 128 rows * 64 = 8192
#define SW_OFF (SC_OFF + CHALF * 64)              // 256 * 8 = 2048 (half-swizzled)
#define S2_OFF (SW_OFF + C_N * 8)                 // 128
#define K2_OFF (S2_OFF + CHALF)                   // 128
#define SMEM_FLOATS (K2_OFF + CHALF)              // 14592 floats = 58368 B

typedef unsigned long long ull;

__device__ __forceinline__ ull ffma2(ull a, ull b, ull c) {
    ull d;
    asm("fma.rn.f32x2 %0, %1, %2, %3;" : "=l"(d) : "l"(a), "l"(b), "l"(c));
    return d;
}
__device__ __forceinline__ float2 unpack2(ull v) {
    float2 r;
    asm("mov.b64 {%0, %1}, %2;" : "=f"(r.x), "=f"(r.y) : "l"(v));
    return r;
}
__device__ __forceinline__ ull pack2(float a) {
    ull r;
    asm("mov.b64 %0, {%1, %2};" : "=l"(r) : "f"(a), "f"(a));
    return r;
}
__device__ __forceinline__ float ex2f(float x) {
    float r;
    asm("ex2.approx.f32 %0, %1;" : "=f"(r) : "f"(x));
    return r;
}

// swizzled float offset of (row, d4-group) inside a 64-float-per-row tile
__device__ __forceinline__ int swz(int row, int d4) {
    return row * 64 + ((d4 ^ (row & 7)) << 2);
}

__global__ void __launch_bounds__(THREADS, 3)
fuzzy_kernel(const float* __restrict__ x,
             const float* __restrict__ centers,
             const float* __restrict__ widths,
             const float* __restrict__ rw,
             float* __restrict__ out) {
    extern __shared__ __align__(16) float sm[];

    const int tid = threadIdx.x;
    const int tx = tid & 7;          // cluster lane 0..7 (phase-contiguous)
    const int ty = tid >> 3;         // row group 0..15
    const int rowbase = blockIdx.x * TILE_ROWS;

    // ---- one-time loads: x tile (swizzled) and rule weights (half-swizzled) ----
    {
        const float4* xg = reinterpret_cast<const float4*>(x) + (size_t)rowbase * 16;
#pragma unroll
        for (int i = 0; i < 8; i++) {
            int idx = tid + i * THREADS;
            int r = idx >> 4, d4 = idx & 15;
            *reinterpret_cast<float4*>(&sm[SX_OFF + swz(r, d4)]) = xg[idx];
        }
        const float4* rg = reinterpret_cast<const float4*>(rw);
#pragma unroll
        for (int i = 0; i < 4; i++) {
            int idx = tid + i * THREADS;
            int c = idx >> 1, h = idx & 1;
            int ph = (h ^ ((c >> 2) & 1)) << 2;   // half-swizzle breaks tx conflicts
            *reinterpret_cast<float4*>(&sm[SW_OFF + c * 8 + ph]) = rg[idx];
        }
    }
    __syncthreads();

    // ---- x_sq for this thread's TR rows (broadcast reads, conflict-free) ----
    float xsq[TR];
#pragma unroll
    for (int r = 0; r < TR; r++) {
        int row = ty * TR + r;
        float a = 0.f;
#pragma unroll
        for (int d4 = 0; d4 < 16; d4++) {
            float4 v = *reinterpret_cast<const float4*>(&sm[SX_OFF + swz(row, d4)]);
            a = fmaf(v.x, v.x, a);
            a = fmaf(v.y, v.y, a);
            a = fmaf(v.z, v.z, a);
            a = fmaf(v.w, v.w, a);
        }
        xsq[r] = a;
    }

    // ---- accumulators across all clusters ----
    float den[TR];
    ull num2[TR][4];
#pragma unroll
    for (int r = 0; r < TR; r++) {
        den[r] = 0.f;
#pragma unroll
        for (int k = 0; k < 4; k++) num2[r][k] = 0ull;
    }

    const int b = (tx >> 2) & 1;          // rw half-swizzle bit for this thread
    const int boff0 = b << 2;             // where outs 0-3 live
    const int boff1 = 4 - (b << 2);       // where outs 4-7 live

    // ================= outer: two 128-cluster chunks =================
    for (int outer = 0; outer < 2; outer++) {
        // load centers chunk (swizzled)
        {
            const float4* cg = reinterpret_cast<const float4*>(centers) + outer * (CHALF * 16);
#pragma unroll
            for (int i = 0; i < 16; i++) {
                int idx = tid + i * THREADS;
                int c = idx >> 4, d4 = idx & 15;
                *reinterpret_cast<float4*>(&sm[SC_OFF + swz(c, d4)]) = cg[idx];
            }
        }
        __syncthreads();

        // per-cluster constants for this chunk (thread tid <-> local cluster tid)
        {
            float csq = 0.f;
#pragma unroll
            for (int d4 = 0; d4 < 16; d4++) {
                float4 v = *reinterpret_cast<const float4*>(&sm[SC_OFF + swz(tid, d4)]);
                csq = fmaf(v.x, v.x, csq);
                csq = fmaf(v.y, v.y, csq);
                csq = fmaf(v.z, v.z, csq);
                csq = fmaf(v.w, v.w, csq);
            }
            float w = widths[outer * CHALF + tid];
            const float LOG2E = 1.4426950408889634f;
            float s = LOG2E / (2.f * w * w);
            sm[S2_OFF + tid] = s;
            sm[K2_OFF + tid] = -csq * s;
        }
        __syncthreads();

        // ---- inner: two 64-cluster register-tile chunks ----
#pragma unroll
        for (int inner = 0; inner < 2; inner++) {
            const int cb = inner * 64;    // local cluster base

            ull acc[TR][TC];
#pragma unroll
            for (int r = 0; r < TR; r++)
#pragma unroll
                for (int j = 0; j < TC; j++) acc[r][j] = 0ull;

#pragma unroll 4
            for (int d4 = 0; d4 < 16; d4++) {
                ulonglong2 xv[TR];
#pragma unroll
                for (int r = 0; r < TR; r++) {
                    int row = ty * TR + r;
                    xv[r] = *reinterpret_cast<const ulonglong2*>(&sm[SX_OFF + swz(row, d4)]);
                }
#pragma unroll
                for (int j = 0; j < TC; j++) {
                    int c = cb + j * 8 + tx;           // c & 7 == tx -> conflict-free
                    ulonglong2 cv = *reinterpret_cast<const ulonglong2*>(
                        &sm[SC_OFF + c * 64 + ((d4 ^ tx) << 2)]);
#pragma unroll
                    for (int r = 0; r < TR; r++) {
                        acc[r][j] = ffma2(xv[r].x, cv.x, acc[r][j]);
                        acc[r][j] = ffma2(xv[r].y, cv.y, acc[r][j]);
                    }
                }
            }

            // epilogue: membership + accumulate den / num
#pragma unroll
            for (int j = 0; j < TC; j++) {
                int c = cb + j * 8 + tx;               // local cluster
                int cg = outer * CHALF + c;            // global cluster
                float s2 = sm[S2_OFF + c];
                float kk = sm[K2_OFF + c];
                ulonglong2 wa = *reinterpret_cast<const ulonglong2*>(&sm[SW_OFF + cg * 8 + boff0]);
                ulonglong2 wb = *reinterpret_cast<const ulonglong2*>(&sm[SW_OFF + cg * 8 + boff1]);
#pragma unroll
                for (int r = 0; r < TR; r++) {
                    float2 u = unpack2(acc[r][j]);
                    float cross = u.x + u.y;
                    float t = fmaf(cross, 2.0f, -xsq[r]);
                    float lg = fmaf(s2, t, kk);
                    float m = ex2f(lg);
                    den[r] += m;
                    ull mm = pack2(m);
                    num2[r][0] = ffma2(mm, wa.x, num2[r][0]);
                    num2[r][1] = ffma2(mm, wa.y, num2[r][1]);
                    num2[r][2] = ffma2(mm, wb.x, num2[r][2]);
                    num2[r][3] = ffma2(mm, wb.y, num2[r][3]);
                }
            }
        }
        __syncthreads();   // protect sc/s2c/k2n before next chunk overwrite
    }

    // ---- cross-tx reduction via shfl (tx lanes are lane bits 0..2) ----
    float nf[TR][8];
#pragma unroll
    for (int r = 0; r < TR; r++)
#pragma unroll
        for (int k = 0; k < 4; k++) {
            float2 u = unpack2(num2[r][k]);
            nf[r][2 * k]     = u.x;
            nf[r][2 * k + 1] = u.y;
        }
#pragma unroll
    for (int s = 1; s < 8; s <<= 1) {
#pragma unroll
        for (int r = 0; r < TR; r++) {
            den[r] += __shfl_xor_sync(0xffffffffu, den[r], s);
#pragma unroll
            for (int k = 0; k < 8; k++)
                nf[r][k] += __shfl_xor_sync(0xffffffffu, nf[r][k], s);
        }
    }

    // each thread writes one coalesced float4: row = ty*TR + (tx>>1), half = tx&1
    {
        int rsel = tx >> 1;
        int h = tx & 1;
        float inv = 1.0f / den[rsel];
        float4 o;
        o.x = nf[rsel][h * 4 + 0] * inv;
        o.y = nf[rsel][h * 4 + 1] * inv;
        o.z = nf[rsel][h * 4 + 2] * inv;
        o.w = nf[rsel][h * 4 + 3] * inv;
        reinterpret_cast<float4*>(out)[((size_t)rowbase + ty * TR + rsel) * 2 + h] = o;
    }
}

extern "C" void kernel_launch(void* const* d_in, const int* in_sizes, int n_in,
                              void* d_out, int out_size) {
    const float* x       = (const float*)d_in[0];
    const float* centers = (const float*)d_in[1];
    const float* widths  = (const float*)d_in[2];
    const float* rw      = (const float*)d_in[3];
    float* out = (float*)d_out;

    size_t smem_bytes = (size_t)SMEM_FLOATS * sizeof(float);   // 58368 B
    cudaFuncSetAttribute(fuzzy_kernel,
                         cudaFuncAttributeMaxDynamicSharedMemorySize,
                         (int)smem_bytes);
    fuzzy_kernel<<<GRID, THREADS, smem_bytes>>>(x, centers, widths, rw, out);
}

// round 7
// speedup vs baseline: 8.1825x; 1.9049x over previous
#include <cuda_runtime.h>
#include <cuda_bf16.h>
#include <cstdint>

#define B_N 262144
#define C_N 256
#define D_N 64
#define O_N 8
#define NTILES 2048          // B_N / 128
#define NCTA 296             // 2 per SM, persistent
#define THREADS 256

// ---- shared memory byte offsets ----
#define OFF_CHI 0            // 256 x 128B bf16 (centers hi)      32768
#define OFF_CLO 32768        // centers lo                        32768
#define OFF_XHI 65536        // 128 x 128B bf16 (x hi)            16384
#define OFF_XLO 81920        // x lo                              16384
#define OFF_SK  98304        // 256 x float2 (s2, k2)              2048
#define OFF_RW  100352       // 256 x 8 f32                        8192
#define OFF_XSQ 108544       // 128 f32                             512
#define SMEM_BYTES 109056

typedef unsigned long long ull;

static __device__ __forceinline__ uint32_t smem_u32(const void* p) {
    uint32_t a;
    asm("{ .reg .u64 t; cvta.to.shared.u64 t, %1; cvt.u32.u64 %0, t; }"
        : "=r"(a) : "l"(p));
    return a;
}
static __device__ __forceinline__ float ex2f(float x) {
    float r; asm("ex2.approx.f32 %0, %1;" : "=f"(r) : "f"(x)); return r;
}
static __device__ __forceinline__ ull ffma2(ull a, ull b, ull c) {
    ull d; asm("fma.rn.f32x2 %0, %1, %2, %3;" : "=l"(d) : "l"(a), "l"(b), "l"(c));
    return d;
}
static __device__ __forceinline__ float2 unpack2(ull v) {
    float2 r; asm("mov.b64 {%0, %1}, %2;" : "=f"(r.x), "=f"(r.y) : "l"(v)); return r;
}
static __device__ __forceinline__ ull pack2(float a) {
    ull r; asm("mov.b64 %0, {%1, %2};" : "=l"(r) : "f"(a), "f"(a)); return r;
}

// swizzled byte address of a 16B granule: row stride 128B, XOR swizzle on quads
static __device__ __forceinline__ uint32_t swz(uint32_t base, int row, int kb) {
    return base + row * 128 + (kb ^ ((row & 7) << 4));
}

static __device__ __forceinline__ void ldsm4(uint32_t& r0, uint32_t& r1,
                                             uint32_t& r2, uint32_t& r3,
                                             uint32_t a) {
    asm volatile("ldmatrix.sync.aligned.m8n8.x4.shared.b16 {%0,%1,%2,%3}, [%4];"
                 : "=r"(r0), "=r"(r1), "=r"(r2), "=r"(r3) : "r"(a));
}

static __device__ __forceinline__ void mma16816(float* d, const uint32_t* a,
                                                uint32_t b0, uint32_t b1) {
    asm volatile(
        "mma.sync.aligned.m16n8k16.row.col.f32.bf16.bf16.f32 "
        "{%0,%1,%2,%3}, {%4,%5,%6,%7}, {%8,%9}, {%0,%1,%2,%3};"
        : "+f"(d[0]), "+f"(d[1]), "+f"(d[2]), "+f"(d[3])
        : "r"(a[0]), "r"(a[1]), "r"(a[2]), "r"(a[3]), "r"(b0), "r"(b1));
}

// split 2 floats into packed bf16 hi pair + lo (residual) pair
static __device__ __forceinline__ void split2(float f0, float f1,
                                              uint32_t& hi, uint32_t& lo) {
    __nv_bfloat16 b0 = __float2bfloat16_rn(f0);
    __nv_bfloat16 b1 = __float2bfloat16_rn(f1);
    float l0 = f0 - __bfloat162float(b0);
    float l1 = f1 - __bfloat162float(b1);
    __nv_bfloat162 hp; hp.x = b0; hp.y = b1;
    __nv_bfloat162 lp = __floats2bfloat162_rn(l0, l1);
    hi = *reinterpret_cast<uint32_t*>(&hp);
    lo = *reinterpret_cast<uint32_t*>(&lp);
}

// convert 32 floats (half a row) -> 4 hi + 4 lo 16B chunks, swizzled store
static __device__ __forceinline__ void store_half_row(char* smemc, uint32_t hibase,
                                                      uint32_t lobase, int row,
                                                      int h, const float* f) {
#pragma unroll
    for (int g = 0; g < 4; g++) {
        uint4 hu, lu;
#pragma unroll
        for (int q = 0; q < 4; q++) {
            uint32_t hv, lv;
            split2(f[g * 8 + 2 * q], f[g * 8 + 2 * q + 1], hv, lv);
            (&hu.x)[q] = hv;
            (&lu.x)[q] = lv;
        }
        int kb = h * 64 + g * 16;
        int off = row * 128 + (kb ^ ((row & 7) << 4));
        *reinterpret_cast<uint4*>(smemc + hibase + off) = hu;
        *reinterpret_cast<uint4*>(smemc + lobase + off) = lu;
    }
}

__global__ void __launch_bounds__(THREADS, 2)
fuzzy_mma(const float* __restrict__ x,
          const float* __restrict__ centers,
          const float* __restrict__ widths,
          const float* __restrict__ rw,
          float* __restrict__ out) {
    extern __shared__ __align__(1024) char smemc[];
    float* smf = reinterpret_cast<float*>(smemc);
    const uint32_t su = smem_u32(smemc);
    const int tid = threadIdx.x;
    const int wid = tid >> 5;
    const int lane = tid & 31;
    const int bid = blockIdx.x;

    // ================= one-time: centers -> bf16 hi/lo, sk, rw =================
    {
        int r2 = tid >> 1, h = tid & 1;
#pragma unroll
        for (int rr = 0; rr < 2; rr++) {
            int row = r2 + rr * 128;
            const float4* cg = reinterpret_cast<const float4*>(
                centers + (size_t)row * D_N + h * 32);
            float f[32];
#pragma unroll
            for (int i = 0; i < 8; i++) {
                float4 v = cg[i];
                f[4 * i] = v.x; f[4 * i + 1] = v.y;
                f[4 * i + 2] = v.z; f[4 * i + 3] = v.w;
            }
            float p = 0.f;
#pragma unroll
            for (int i = 0; i < 32; i++) p = fmaf(f[i], f[i], p);
            p += __shfl_xor_sync(0xffffffffu, p, 1);
            if (h == 0) {
                float w = widths[row];
                const float LOG2E = 1.4426950408889634f;
                float s = LOG2E / (2.f * w * w);
                smf[OFF_SK / 4 + 2 * row] = s;
                smf[OFF_SK / 4 + 2 * row + 1] = -p * s;
            }
            store_half_row(smemc, OFF_CHI, OFF_CLO, row, h, f);
        }
        // rule weights: 512 float4
        const float4* rg = reinterpret_cast<const float4*>(rw);
        float4* rs = reinterpret_cast<float4*>(smemc + OFF_RW);
        rs[tid] = rg[tid];
        rs[tid + 256] = rg[tid + 256];
    }
    __syncthreads();

    const int m0 = wid * 16;
    // ldmatrix lane address components (constant per thread)
    const int la_row = ((lane >> 3) & 1) * 8 + (lane & 7);   // A: row within 16
    const int la_k16 = (lane >> 4);                          // A: +16B for k+8 tiles
    const int lb_row = lane & 7;                             // B: n within 8
    const int lb_k16 = (lane >> 3);                          // B: 16B granule 0..3

    // ================= persistent tile loop =================
    for (int tile = bid; tile < NTILES; tile += NCTA) {
        // ---- stage x tile (bf16 hi/lo + xsq) ----
        {
            int r = tid >> 1, h = tid & 1;
            const float4* xg = reinterpret_cast<const float4*>(
                x + ((size_t)tile * 128 + r) * D_N + h * 32);
            float f[32];
#pragma unroll
            for (int i = 0; i < 8; i++) {
                float4 v = xg[i];
                f[4 * i] = v.x; f[4 * i + 1] = v.y;
                f[4 * i + 2] = v.z; f[4 * i + 3] = v.w;
            }
            float p = 0.f;
#pragma unroll
            for (int i = 0; i < 32; i++) p = fmaf(f[i], f[i], p);
            p += __shfl_xor_sync(0xffffffffu, p, 1);
            if (h == 0) smf[OFF_XSQ / 4 + r] = p;
            store_half_row(smemc, OFF_XHI, OFF_XLO, r, h, f);
        }
        __syncthreads();

        // ---- load A fragments (warp-private rows, once per tile) ----
        uint32_t ah[16], al[16];
#pragma unroll
        for (int s = 0; s < 4; s++) {
            int row = m0 + la_row;
            int kb = s * 32 + la_k16 * 16;
            ldsm4(ah[4 * s], ah[4 * s + 1], ah[4 * s + 2], ah[4 * s + 3],
                  swz(su + OFF_XHI, row, kb));
            ldsm4(al[4 * s], al[4 * s + 1], al[4 * s + 2], al[4 * s + 3],
                  swz(su + OFF_XLO, row, kb));
        }
        float xs0 = smf[OFF_XSQ / 4 + m0 + (lane >> 2)];
        float xs1 = smf[OFF_XSQ / 4 + m0 + (lane >> 2) + 8];

        float den0 = 0.f, den1 = 0.f;
        ull num0[4] = {0, 0, 0, 0};
        ull num1[4] = {0, 0, 0, 0};

        // ---- n-block loop over 256 clusters ----
#pragma unroll 2
        for (int nb = 0; nb < 32; nb++) {
            const int n0 = nb * 8;
            uint32_t bh[8], bl[8];
#pragma unroll
            for (int p = 0; p < 2; p++) {
                int row = n0 + lb_row;
                int kb = p * 64 + lb_k16 * 16;
                ldsm4(bh[4 * p], bh[4 * p + 1], bh[4 * p + 2], bh[4 * p + 3],
                      swz(su + OFF_CHI, row, kb));
                ldsm4(bl[4 * p], bl[4 * p + 1], bl[4 * p + 2], bl[4 * p + 3],
                      swz(su + OFF_CLO, row, kb));
            }
            float acc[4] = {0.f, 0.f, 0.f, 0.f};
            // kstep s fragment regs: index (s/2)*4 + (s%2)*2
#pragma unroll
            for (int s = 0; s < 4; s++) {
                int bi = (s >> 1) * 4 + (s & 1) * 2;
                mma16816(acc, &ah[4 * s], bh[bi], bh[bi + 1]);
            }
#pragma unroll
            for (int s = 0; s < 4; s++) {
                int bi = (s >> 1) * 4 + (s & 1) * 2;
                mma16816(acc, &ah[4 * s], bl[bi], bl[bi + 1]);
            }
#pragma unroll
            for (int s = 0; s < 4; s++) {
                int bi = (s >> 1) * 4 + (s & 1) * 2;
                mma16816(acc, &al[4 * s], bh[bi], bh[bi + 1]);
            }

            // ---- fused epilogue: memb + den/num accumulation ----
            int cA = n0 + 2 * (lane & 3);
            float2 skA = *reinterpret_cast<const float2*>(&smf[OFF_SK / 4 + 2 * cA]);
            float2 skB = *reinterpret_cast<const float2*>(&smf[OFF_SK / 4 + 2 * cA + 2]);
            float m00 = ex2f(fmaf(skA.x, fmaf(acc[0], 2.f, -xs0), skA.y));
            float m01 = ex2f(fmaf(skB.x, fmaf(acc[1], 2.f, -xs0), skB.y));
            float m10 = ex2f(fmaf(skA.x, fmaf(acc[2], 2.f, -xs1), skA.y));
            float m11 = ex2f(fmaf(skB.x, fmaf(acc[3], 2.f, -xs1), skB.y));
            den0 += m00 + m01;
            den1 += m10 + m11;
            const ulonglong2* wrA =
                reinterpret_cast<const ulonglong2*>(smemc + OFF_RW + cA * 32);
            ulonglong2 wA0 = wrA[0], wA1 = wrA[1];
            ulonglong2 wB0 = wrA[2], wB1 = wrA[3];
            ull mA0 = pack2(m00), mB0 = pack2(m01);
            ull mA1 = pack2(m10), mB1 = pack2(m11);
            num0[0] = ffma2(mA0, wA0.x, num0[0]);
            num0[1] = ffma2(mA0, wA0.y, num0[1]);
            num0[2] = ffma2(mA0, wA1.x, num0[2]);
            num0[3] = ffma2(mA0, wA1.y, num0[3]);
            num0[0] = ffma2(mB0, wB0.x, num0[0]);
            num0[1] = ffma2(mB0, wB0.y, num0[1]);
            num0[2] = ffma2(mB0, wB1.x, num0[2]);
            num0[3] = ffma2(mB0, wB1.y, num0[3]);
            num1[0] = ffma2(mA1, wA0.x, num1[0]);
            num1[1] = ffma2(mA1, wA0.y, num1[1]);
            num1[2] = ffma2(mA1, wA1.x, num1[2]);
            num1[3] = ffma2(mA1, wA1.y, num1[3]);
            num1[0] = ffma2(mB1, wB0.x, num1[0]);
            num1[1] = ffma2(mB1, wB0.y, num1[1]);
            num1[2] = ffma2(mB1, wB1.x, num1[2]);
            num1[3] = ffma2(mB1, wB1.y, num1[3]);
        }

        // ---- reduce across the 4 lanes of each quad (lane bits 0..1) ----
#pragma unroll
        for (int s = 1; s < 4; s <<= 1) {
            den0 += __shfl_xor_sync(0xffffffffu, den0, s);
            den1 += __shfl_xor_sync(0xffffffffu, den1, s);
#pragma unroll
            for (int k = 0; k < 4; k++) {
                float2 u0 = unpack2(num0[k]);
                float2 u1 = unpack2(num1[k]);
                u0.x += __shfl_xor_sync(0xffffffffu, u0.x, s);
                u0.y += __shfl_xor_sync(0xffffffffu, u0.y, s);
                u1.x += __shfl_xor_sync(0xffffffffu, u1.x, s);
                u1.y += __shfl_xor_sync(0xffffffffu, u1.y, s);
                asm("mov.b64 %0, {%1, %2};" : "=l"(num0[k]) : "f"(u0.x), "f"(u0.y));
                asm("mov.b64 %0, {%1, %2};" : "=l"(num1[k]) : "f"(u1.x), "f"(u1.y));
            }
        }

        if ((lane & 3) == 0) {
            int rowl = m0 + (lane >> 2);
            size_t gr = (size_t)tile * 128 + rowl;
            float inv0 = 1.0f / den0;
            float inv1 = 1.0f / den1;
            float2 u;
            float4 o;
            float4* go0 = reinterpret_cast<float4*>(out + gr * O_N);
            u = unpack2(num0[0]); o.x = u.x * inv0; o.y = u.y * inv0;
            u = unpack2(num0[1]); o.z = u.x * inv0; o.w = u.y * inv0;
            go0[0] = o;
            u = unpack2(num0[2]); o.x = u.x * inv0; o.y = u.y * inv0;
            u = unpack2(num0[3]); o.z = u.x * inv0; o.w = u.y * inv0;
            go0[1] = o;
            float4* go1 = reinterpret_cast<float4*>(out + (gr + 8) * O_N);
            u = unpack2(num1[0]); o.x = u.x * inv1; o.y = u.y * inv1;
            u = unpack2(num1[1]); o.z = u.x * inv1; o.w = u.y * inv1;
            go1[0] = o;
            u = unpack2(num1[2]); o.x = u.x * inv1; o.y = u.y * inv1;
            u = unpack2(num1[3]); o.z = u.x * inv1; o.w = u.y * inv1;
            go1[1] = o;
        }
        __syncthreads();   // protect x tile before next stage
    }
}

extern "C" void kernel_launch(void* const* d_in, const int* in_sizes, int n_in,
                              void* d_out, int out_size) {
    const float* x       = (const float*)d_in[0];
    const float* centers = (const float*)d_in[1];
    const float* widths  = (const float*)d_in[2];
    const float* rw      = (const float*)d_in[3];
    float* out = (float*)d_out;

    cudaFuncSetAttribute(fuzzy_mma,
                         cudaFuncAttributeMaxDynamicSharedMemorySize, SMEM_BYTES);
    fuzzy_mma<<<NCTA, THREADS, SMEM_BYTES>>>(x, centers, widths, rw, out);
}

// round 10
// speedup vs baseline: 9.8649x; 1.2056x over previous
#include <cuda_runtime.h>
#include <cuda_bf16.h>
#include <cstdint>

#define B_N 262144
#define C_N 256
#define D_N 64
#define O_N 8
#define NTILES 2048          // B_N / 128
#define NCTA 296             // 2 per SM, persistent
#define THREADS 128          // 4 warps, 32 rows each

// ---- shared memory byte offsets ----
#define OFF_CHI 0            // centers hi bf16: 256 rows x 128B   32768
#define OFF_CLO 32768        // centers lo                         32768
#define OFF_XHI 65536        // x hi: 128 rows x 128B              16384
#define OFF_XLO 81920        // x lo                               16384
#define OFF_SK  98304        // 256 x float2 (s2, k2)               2048
#define OFF_RW  100352       // permuted [nb][k][lq] 16B chunks     8192
#define OFF_XSQ 108544       // 128 f32                              512
#define SMEM_BYTES 109056

typedef unsigned long long ull;

static __device__ __forceinline__ uint32_t smem_u32(const void* p) {
    uint32_t a;
    asm("{ .reg .u64 t; cvta.to.shared.u64 t, %1; cvt.u32.u64 %0, t; }"
        : "=r"(a) : "l"(p));
    return a;
}
static __device__ __forceinline__ float ex2f(float x) {
    float r; asm("ex2.approx.f32 %0, %1;" : "=f"(r) : "f"(x)); return r;
}
static __device__ __forceinline__ ull ffma2(ull a, ull b, ull c) {
    ull d; asm("fma.rn.f32x2 %0, %1, %2, %3;" : "=l"(d) : "l"(a), "l"(b), "l"(c));
    return d;
}
static __device__ __forceinline__ float2 unpack2(ull v) {
    float2 r; asm("mov.b64 {%0, %1}, %2;" : "=f"(r.x), "=f"(r.y) : "l"(v)); return r;
}
static __device__ __forceinline__ ull pack2(float a) {
    ull r; asm("mov.b64 %0, {%1, %2};" : "=l"(r) : "f"(a), "f"(a)); return r;
}

// swizzled byte address of a 16B granule: row stride 128B, XOR swizzle on quads
static __device__ __forceinline__ uint32_t swz(uint32_t base, int row, int kb) {
    return base + row * 128 + (kb ^ ((row & 7) << 4));
}

static __device__ __forceinline__ void ldsm4(uint32_t& r0, uint32_t& r1,
                                             uint32_t& r2, uint32_t& r3,
                                             uint32_t a) {
    asm volatile("ldmatrix.sync.aligned.m8n8.x4.shared.b16 {%0,%1,%2,%3}, [%4];"
                 : "=r"(r0), "=r"(r1), "=r"(r2), "=r"(r3) : "r"(a));
}

static __device__ __forceinline__ void mma16816(float* d, const uint32_t* a,
                                                uint32_t b0, uint32_t b1) {
    asm volatile(
        "mma.sync.aligned.m16n8k16.row.col.f32.bf16.bf16.f32 "
        "{%0,%1,%2,%3}, {%4,%5,%6,%7}, {%8,%9}, {%0,%1,%2,%3};"
        : "+f"(d[0]), "+f"(d[1]), "+f"(d[2]), "+f"(d[3])
        : "r"(a[0]), "r"(a[1]), "r"(a[2]), "r"(a[3]), "r"(b0), "r"(b1));
}

// split 2 floats into packed bf16 hi pair + lo (residual) pair
static __device__ __forceinline__ void split2(float f0, float f1,
                                              uint32_t& hi, uint32_t& lo) {
    __nv_bfloat16 b0 = __float2bfloat16_rn(f0);
    __nv_bfloat16 b1 = __float2bfloat16_rn(f1);
    float l0 = f0 - __bfloat162float(b0);
    float l1 = f1 - __bfloat162float(b1);
    __nv_bfloat162 hp; hp.x = b0; hp.y = b1;
    __nv_bfloat162 lp = __floats2bfloat162_rn(l0, l1);
    hi = *reinterpret_cast<uint32_t*>(&hp);
    lo = *reinterpret_cast<uint32_t*>(&lp);
}

// stage one float4 (quad q of a 64-float row) as bf16 hi/lo, swizzled
static __device__ __forceinline__ void stage_f4(char* smemc, uint32_t hibase,
                                                uint32_t lobase, int row, int q,
                                                float4 v) {
    uint32_t h0, l0, h1, l1;
    split2(v.x, v.y, h0, l0);
    split2(v.z, v.w, h1, l1);
    int off = row * 128 + (((q >> 1) * 16) ^ ((row & 7) << 4)) + (q & 1) * 8;
    *reinterpret_cast<uint2*>(smemc + hibase + off) = make_uint2(h0, h1);
    *reinterpret_cast<uint2*>(smemc + lobase + off) = make_uint2(l0, l1);
}

__global__ void __launch_bounds__(THREADS, 2)
fuzzy_mma(const float* __restrict__ x,
          const float* __restrict__ centers,
          const float* __restrict__ widths,
          const float* __restrict__ rw,
          float* __restrict__ out) {
    extern __shared__ __align__(1024) char smemc[];
    float* smf = reinterpret_cast<float*>(smemc);
    const uint32_t su = smem_u32(smemc);
    const int tid = threadIdx.x;
    const int wid = tid >> 5;
    const int lane = tid & 31;
    const int lq = lane & 3;
    const int bid = blockIdx.x;

    // ========== one-time: centers -> bf16 hi/lo (coalesced), sk, rw ==========
    {
        const float4* cg = reinterpret_cast<const float4*>(centers);
        const float LOG2E = 1.4426950408889634f;
#pragma unroll 4
        for (int i = 0; i < 32; i++) {
            int j = tid + i * THREADS;          // float4 index, 4096 total
            float4 v = cg[j];
            float p = v.x * v.x;
            p = fmaf(v.y, v.y, p);
            p = fmaf(v.z, v.z, p);
            p = fmaf(v.w, v.w, p);
            p += __shfl_xor_sync(0xffffffffu, p, 1);
            p += __shfl_xor_sync(0xffffffffu, p, 2);
            p += __shfl_xor_sync(0xffffffffu, p, 4);
            p += __shfl_xor_sync(0xffffffffu, p, 8);
            stage_f4(smemc, OFF_CHI, OFF_CLO, j >> 4, j & 15, v);
            if ((tid & 15) == 0) {
                int row = j >> 4;
                float w = widths[row];
                float s = LOG2E / (2.f * w * w);
                smf[OFF_SK / 4 + 2 * row] = s;
                smf[OFF_SK / 4 + 2 * row + 1] = -p * s;
            }
        }
        // rw permuted: new[nb*16 + k*4 + lq] = orig[nb*16 + lq*4 + k]
        const float4* rg = reinterpret_cast<const float4*>(rw);
        float4* rs = reinterpret_cast<float4*>(smemc + OFF_RW);
#pragma unroll
        for (int i = 0; i < 4; i++) {
            int n = tid + i * THREADS;
            int orig = (n & ~15) | ((n & 3) << 2) | ((n >> 2) & 3);
            rs[n] = rg[orig];
        }
    }
    __syncthreads();

    // ldmatrix lane address components (constant per thread)
    const int la_row = ((lane >> 3) & 1) * 8 + (lane & 7);   // A: row within 16
    const int la_k16 = (lane >> 4);                          // A: +16B for k+8
    const int lb_row = lane & 7;                             // B: n within 8
    const int lb_k16 = (lane >> 3);                          // B: granule 0..3
    const int m0 = wid * 32;

    // ================= persistent tile loop =================
    for (int tile = bid; tile < NTILES; tile += NCTA) {
        // ---- stage x tile: coalesced read + shfl xsq + swizzled store ----
        {
            const float4* xg = reinterpret_cast<const float4*>(x) + (size_t)tile * 2048;
#pragma unroll 4
            for (int i = 0; i < 16; i++) {
                int j = tid + i * THREADS;
                float4 v = xg[j];
                float p = v.x * v.x;
                p = fmaf(v.y, v.y, p);
                p = fmaf(v.z, v.z, p);
                p = fmaf(v.w, v.w, p);
                p += __shfl_xor_sync(0xffffffffu, p, 1);
                p += __shfl_xor_sync(0xffffffffu, p, 2);
                p += __shfl_xor_sync(0xffffffffu, p, 4);
                p += __shfl_xor_sync(0xffffffffu, p, 8);
                stage_f4(smemc, OFF_XHI, OFF_XLO, j >> 4, j & 15, v);
                if ((tid & 15) == 0) smf[OFF_XSQ / 4 + (j >> 4)] = p;
            }
        }
        __syncthreads();

        // ---- A fragments: 32 rows per warp = two 16-row groups ----
        uint32_t ah0[16], al0[16], ah1[16], al1[16];
#pragma unroll
        for (int s = 0; s < 4; s++) {
            int r0 = m0 + la_row;
            int r1 = r0 + 16;
            int kb = s * 32 + la_k16 * 16;
            ldsm4(ah0[4 * s], ah0[4 * s + 1], ah0[4 * s + 2], ah0[4 * s + 3],
                  swz(su + OFF_XHI, r0, kb));
            ldsm4(al0[4 * s], al0[4 * s + 1], al0[4 * s + 2], al0[4 * s + 3],
                  swz(su + OFF_XLO, r0, kb));
            ldsm4(ah1[4 * s], ah1[4 * s + 1], ah1[4 * s + 2], ah1[4 * s + 3],
                  swz(su + OFF_XHI, r1, kb));
            ldsm4(al1[4 * s], al1[4 * s + 1], al1[4 * s + 2], al1[4 * s + 3],
                  swz(su + OFF_XLO, r1, kb));
        }
        float xs0 = smf[OFF_XSQ / 4 + m0 + (lane >> 2)];
        float xs1 = smf[OFF_XSQ / 4 + m0 + (lane >> 2) + 8];
        float xs2 = smf[OFF_XSQ / 4 + m0 + (lane >> 2) + 16];
        float xs3 = smf[OFF_XSQ / 4 + m0 + (lane >> 2) + 24];

        float den0 = 0.f, den1 = 0.f, den2 = 0.f, den3 = 0.f;
        ull num0[4] = {0, 0, 0, 0};
        ull num1[4] = {0, 0, 0, 0};
        ull num2[4] = {0, 0, 0, 0};
        ull num3[4] = {0, 0, 0, 0};

        // ---- n-block loop over 256 clusters ----
#pragma unroll 2
        for (int nb = 0; nb < 32; nb++) {
            const int n0 = nb * 8;
            uint32_t bh[8], bl[8];
#pragma unroll
            for (int p = 0; p < 2; p++) {
                int row = n0 + lb_row;
                int kb = p * 64 + lb_k16 * 16;
                ldsm4(bh[4 * p], bh[4 * p + 1], bh[4 * p + 2], bh[4 * p + 3],
                      swz(su + OFF_CHI, row, kb));
                ldsm4(bl[4 * p], bl[4 * p + 1], bl[4 * p + 2], bl[4 * p + 3],
                      swz(su + OFF_CLO, row, kb));
            }
            // sk for clusters cA=n0+2lq, cA+1 : one conflict-free LDS.128
            float4 skv = *reinterpret_cast<const float4*>(
                smemc + OFF_SK + n0 * 8 + lq * 16);
            // rw (permuted): 4 broadcast LDS.128
            const ulonglong2* wp = reinterpret_cast<const ulonglong2*>(
                smemc + OFF_RW + nb * 256 + lq * 16);
            ulonglong2 w0 = wp[0];
            ulonglong2 w1 = wp[4];
            ulonglong2 w2 = wp[8];
            ulonglong2 w3 = wp[12];

            float acc0[4] = {0.f, 0.f, 0.f, 0.f};
            float acc1[4] = {0.f, 0.f, 0.f, 0.f};
#pragma unroll
            for (int s = 0; s < 4; s++) {
                int bi = (s >> 1) * 4 + (s & 1) * 2;
                mma16816(acc0, &ah0[4 * s], bh[bi], bh[bi + 1]);
                mma16816(acc1, &ah1[4 * s], bh[bi], bh[bi + 1]);
            }
#pragma unroll
            for (int s = 0; s < 4; s++) {
                int bi = (s >> 1) * 4 + (s & 1) * 2;
                mma16816(acc0, &ah0[4 * s], bl[bi], bl[bi + 1]);
                mma16816(acc1, &ah1[4 * s], bl[bi], bl[bi + 1]);
            }
#pragma unroll
            for (int s = 0; s < 4; s++) {
                int bi = (s >> 1) * 4 + (s & 1) * 2;
                mma16816(acc0, &al0[4 * s], bh[bi], bh[bi + 1]);
                mma16816(acc1, &al1[4 * s], bh[bi], bh[bi + 1]);
            }

            // ---- fused epilogue, group 0 (rows m0.., m0+8..) ----
            {
                float m00 = ex2f(fmaf(skv.x, fmaf(acc0[0], 2.f, -xs0), skv.y));
                float m01 = ex2f(fmaf(skv.z, fmaf(acc0[1], 2.f, -xs0), skv.w));
                float m10 = ex2f(fmaf(skv.x, fmaf(acc0[2], 2.f, -xs1), skv.y));
                float m11 = ex2f(fmaf(skv.z, fmaf(acc0[3], 2.f, -xs1), skv.w));
                den0 += m00 + m01;
                den1 += m10 + m11;
                ull mA0 = pack2(m00), mB0 = pack2(m01);
                ull mA1 = pack2(m10), mB1 = pack2(m11);
                num0[0] = ffma2(mA0, w0.x, num0[0]);
                num0[1] = ffma2(mA0, w0.y, num0[1]);
                num0[2] = ffma2(mA0, w1.x, num0[2]);
                num0[3] = ffma2(mA0, w1.y, num0[3]);
                num0[0] = ffma2(mB0, w2.x, num0[0]);
                num0[1] = ffma2(mB0, w2.y, num0[1]);
                num0[2] = ffma2(mB0, w3.x, num0[2]);
                num0[3] = ffma2(mB0, w3.y, num0[3]);
                num1[0] = ffma2(mA1, w0.x, num1[0]);
                num1[1] = ffma2(mA1, w0.y, num1[1]);
                num1[2] = ffma2(mA1, w1.x, num1[2]);
                num1[3] = ffma2(mA1, w1.y, num1[3]);
                num1[0] = ffma2(mB1, w2.x, num1[0]);
                num1[1] = ffma2(mB1, w2.y, num1[1]);
                num1[2] = ffma2(mB1, w3.x, num1[2]);
                num1[3] = ffma2(mB1, w3.y, num1[3]);
            }
            // ---- fused epilogue, group 1 (rows m0+16.., m0+24..) ----
            {
                float m00 = ex2f(fmaf(skv.x, fmaf(acc1[0], 2.f, -xs2), skv.y));
                float m01 = ex2f(fmaf(skv.z, fmaf(acc1[1], 2.f, -xs2), skv.w));
                float m10 = ex2f(fmaf(skv.x, fmaf(acc1[2], 2.f, -xs3), skv.y));
                float m11 = ex2f(fmaf(skv.z, fmaf(acc1[3], 2.f, -xs3), skv.w));
                den2 += m00 + m01;
                den3 += m10 + m11;
                ull mA0 = pack2(m00), mB0 = pack2(m01);
                ull mA1 = pack2(m10), mB1 = pack2(m11);
                num2[0] = ffma2(mA0, w0.x, num2[0]);
                num2[1] = ffma2(mA0, w0.y, num2[1]);
                num2[2] = ffma2(mA0, w1.x, num2[2]);
                num2[3] = ffma2(mA0, w1.y, num2[3]);
                num2[0] = ffma2(mB0, w2.x, num2[0]);
                num2[1] = ffma2(mB0, w2.y, num2[1]);
                num2[2] = ffma2(mB0, w3.x, num2[2]);
                num2[3] = ffma2(mB0, w3.y, num2[3]);
                num3[0] = ffma2(mA1, w0.x, num3[0]);
                num3[1] = ffma2(mA1, w0.y, num3[1]);
                num3[2] = ffma2(mA1, w1.x, num3[2]);
                num3[3] = ffma2(mA1, w1.y, num3[3]);
                num3[0] = ffma2(mB1, w2.x, num3[0]);
                num3[1] = ffma2(mB1, w2.y, num3[1]);
                num3[2] = ffma2(mB1, w3.x, num3[2]);
                num3[3] = ffma2(mB1, w3.y, num3[3]);
            }
        }

        // ---- quad reduction (lane bits 0..1) ----
#pragma unroll
        for (int s = 1; s < 4; s <<= 1) {
            den0 += __shfl_xor_sync(0xffffffffu, den0, s);
            den1 += __shfl_xor_sync(0xffffffffu, den1, s);
            den2 += __shfl_xor_sync(0xffffffffu, den2, s);
            den3 += __shfl_xor_sync(0xffffffffu, den3, s);
#pragma unroll
            for (int k = 0; k < 4; k++) {
                float2 u;
                u = unpack2(num0[k]);
                u.x += __shfl_xor_sync(0xffffffffu, u.x, s);
                u.y += __shfl_xor_sync(0xffffffffu, u.y, s);
                asm("mov.b64 %0, {%1, %2};" : "=l"(num0[k]) : "f"(u.x), "f"(u.y));
                u = unpack2(num1[k]);
                u.x += __shfl_xor_sync(0xffffffffu, u.x, s);
                u.y += __shfl_xor_sync(0xffffffffu, u.y, s);
                asm("mov.b64 %0, {%1, %2};" : "=l"(num1[k]) : "f"(u.x), "f"(u.y));
                u = unpack2(num2[k]);
                u.x += __shfl_xor_sync(0xffffffffu, u.x, s);
                u.y += __shfl_xor_sync(0xffffffffu, u.y, s);
                asm("mov.b64 %0, {%1, %2};" : "=l"(num2[k]) : "f"(u.x), "f"(u.y));
                u = unpack2(num3[k]);
                u.x += __shfl_xor_sync(0xffffffffu, u.x, s);
                u.y += __shfl_xor_sync(0xffffffffu, u.y, s);
                asm("mov.b64 %0, {%1, %2};" : "=l"(num3[k]) : "f"(u.x), "f"(u.y));
            }
        }

        if ((lane & 3) == 0) {
            size_t gr = (size_t)tile * 128 + m0 + (lane >> 2);
            float inv;
            float2 u;
            float4 o;
            float4* go;
#define WRITE_ROWS(numA, denA, roff)                                        \
            inv = 1.0f / (denA);                                            \
            go = reinterpret_cast<float4*>(out + (gr + (roff)) * O_N);      \
            u = unpack2(numA[0]); o.x = u.x * inv; o.y = u.y * inv;         \
            u = unpack2(numA[1]); o.z = u.x * inv; o.w = u.y * inv;         \
            go[0] = o;                                                      \
            u = unpack2(numA[2]); o.x = u.x * inv; o.y = u.y * inv;         \
            u = unpack2(numA[3]); o.z = u.x * inv; o.w = u.y * inv;         \
            go[1] = o;
            WRITE_ROWS(num0, den0, 0)
            WRITE_ROWS(num1, den1, 8)
            WRITE_ROWS(num2, den2, 16)
            WRITE_ROWS(num3, den3, 24)
#undef WRITE_ROWS
        }
        __syncthreads();   // protect x tile before next stage
    }
}

extern "C" void kernel_launch(void* const* d_in, const int* in_sizes, int n_in,
                              void* d_out, int out_size) {
    const float* x       = (const float*)d_in[0];
    const float* centers = (const float*)d_in[1];
    const float* widths  = (const float*)d_in[2];
    const float* rw      = (const float*)d_in[3];
    float* out = (float*)d_out;

    cudaFuncSetAttribute(fuzzy_mma,
                         cudaFuncAttributeMaxDynamicSharedMemorySize, SMEM_BYTES);
    fuzzy_mma<<<NCTA, THREADS, SMEM_BYTES>>>(x, centers, widths, rw, out);
}

// round 13
// speedup vs baseline: 9.9889x; 1.0126x over previous
#include <cuda_runtime.h>
#include <cuda_bf16.h>
#include <cstdint>

#define B_N 262144
#define C_N 256
#define D_N 64
#define O_N 8
#define NTILES 2048          // B_N / 128
#define NCTA 296             // 2 per SM, persistent
#define THREADS 128          // 4 warps, 32 rows each

// ---- shared memory byte offsets ----
#define OFF_CHI 0            // centers hi bf16: 256 rows x 128B   32768
#define OFF_CLO 32768        // centers lo                         32768
#define OFF_XHI 65536        // x hi: 128 rows x 128B              16384
#define OFF_XLO 81920        // x lo                               16384
#define OFF_SK  98304        // 256 x float2 (s2, k2)               2048
#define OFF_RW  100352       // permuted [nb][k][lq] 16B chunks     8192
#define OFF_XSQ 108544       // 128 f32                              512
#define SMEM_BYTES 109056

typedef unsigned long long ull;

static __device__ __forceinline__ uint32_t smem_u32(const void* p) {
    uint32_t a;
    asm("{ .reg .u64 t; cvta.to.shared.u64 t, %1; cvt.u32.u64 %0, t; }"
        : "=r"(a) : "l"(p));
    return a;
}
static __device__ __forceinline__ float ex2f(float x) {
    float r; asm("ex2.approx.f32 %0, %1;" : "=f"(r) : "f"(x)); return r;
}
static __device__ __forceinline__ ull ffma2(ull a, ull b, ull c) {
    ull d; asm("fma.rn.f32x2 %0, %1, %2, %3;" : "=l"(d) : "l"(a), "l"(b), "l"(c));
    return d;
}
static __device__ __forceinline__ float2 unpack2(ull v) {
    float2 r; asm("mov.b64 {%0, %1}, %2;" : "=f"(r.x), "=f"(r.y) : "l"(v)); return r;
}
static __device__ __forceinline__ ull pack2(float a) {
    ull r; asm("mov.b64 %0, {%1, %2};" : "=l"(r) : "f"(a), "f"(a)); return r;
}

// swizzled byte address of a 16B granule: row stride 128B, XOR swizzle on quads
static __device__ __forceinline__ uint32_t swz(uint32_t base, int row, int kb) {
    return base + row * 128 + (kb ^ ((row & 7) << 4));
}

static __device__ __forceinline__ void ldsm4(uint32_t& r0, uint32_t& r1,
                                             uint32_t& r2, uint32_t& r3,
                                             uint32_t a) {
    asm volatile("ldmatrix.sync.aligned.m8n8.x4.shared.b16 {%0,%1,%2,%3}, [%4];"
                 : "=r"(r0), "=r"(r1), "=r"(r2), "=r"(r3) : "r"(a));
}

static __device__ __forceinline__ void mma16816(float* d, const uint32_t* a,
                                                uint32_t b0, uint32_t b1) {
    asm volatile(
        "mma.sync.aligned.m16n8k16.row.col.f32.bf16.bf16.f32 "
        "{%0,%1,%2,%3}, {%4,%5,%6,%7}, {%8,%9}, {%0,%1,%2,%3};"
        : "+f"(d[0]), "+f"(d[1]), "+f"(d[2]), "+f"(d[3])
        : "r"(a[0]), "r"(a[1]), "r"(a[2]), "r"(a[3]), "r"(b0), "r"(b1));
}

// split 2 floats into packed bf16 hi pair + lo (residual) pair
static __device__ __forceinline__ void split2(float f0, float f1,
                                              uint32_t& hi, uint32_t& lo) {
    __nv_bfloat16 b0 = __float2bfloat16_rn(f0);
    __nv_bfloat16 b1 = __float2bfloat16_rn(f1);
    float l0 = f0 - __bfloat162float(b0);
    float l1 = f1 - __bfloat162float(b1);
    __nv_bfloat162 hp; hp.x = b0; hp.y = b1;
    __nv_bfloat162 lp = __floats2bfloat162_rn(l0, l1);
    hi = *reinterpret_cast<uint32_t*>(&hp);
    lo = *reinterpret_cast<uint32_t*>(&lp);
}

// stage one float4 (quad q of a 64-float row) as bf16 hi/lo, swizzled
static __device__ __forceinline__ void stage_f4(char* smemc, uint32_t hibase,
                                                uint32_t lobase, int row, int q,
                                                float4 v) {
    uint32_t h0, l0, h1, l1;
    split2(v.x, v.y, h0, l0);
    split2(v.z, v.w, h1, l1);
    int off = row * 128 + (((q >> 1) * 16) ^ ((row & 7) << 4)) + (q & 1) * 8;
    *reinterpret_cast<uint2*>(smemc + hibase + off) = make_uint2(h0, h1);
    *reinterpret_cast<uint2*>(smemc + lobase + off) = make_uint2(l0, l1);
}

// per-nb register-resident operands: B fragments + sk + rw
struct BFrag {
    uint32_t bh[8], bl[8];
    float4 skv;
    ulonglong2 w0, w1, w2, w3;
};

__global__ void __launch_bounds__(THREADS, 2)
fuzzy_mma(const float* __restrict__ x,
          const float* __restrict__ centers,
          const float* __restrict__ widths,
          const float* __restrict__ rw,
          float* __restrict__ out) {
    extern __shared__ __align__(1024) char smemc[];
    float* smf = reinterpret_cast<float*>(smemc);
    const uint32_t su = smem_u32(smemc);
    const int tid = threadIdx.x;
    const int wid = tid >> 5;
    const int lane = tid & 31;
    const int lq = lane & 3;
    const int bid = blockIdx.x;

    // ========== one-time: centers -> bf16 hi/lo (coalesced), sk, rw ==========
    {
        const float4* cg = reinterpret_cast<const float4*>(centers);
        const float LOG2E = 1.4426950408889634f;
#pragma unroll 4
        for (int i = 0; i < 32; i++) {
            int j = tid + i * THREADS;          // float4 index, 4096 total
            float4 v = cg[j];
            float p = v.x * v.x;
            p = fmaf(v.y, v.y, p);
            p = fmaf(v.z, v.z, p);
            p = fmaf(v.w, v.w, p);
            p += __shfl_xor_sync(0xffffffffu, p, 1);
            p += __shfl_xor_sync(0xffffffffu, p, 2);
            p += __shfl_xor_sync(0xffffffffu, p, 4);
            p += __shfl_xor_sync(0xffffffffu, p, 8);
            stage_f4(smemc, OFF_CHI, OFF_CLO, j >> 4, j & 15, v);
            if ((tid & 15) == 0) {
                int row = j >> 4;
                float w = widths[row];
                float s = LOG2E / (2.f * w * w);
                smf[OFF_SK / 4 + 2 * row] = s;
                smf[OFF_SK / 4 + 2 * row + 1] = -p * s;
            }
        }
        // rw permuted: new[nb*16 + k*4 + lq] = orig[nb*16 + lq*4 + k]
        const float4* rg = reinterpret_cast<const float4*>(rw);
        float4* rs = reinterpret_cast<float4*>(smemc + OFF_RW);
#pragma unroll
        for (int i = 0; i < 4; i++) {
            int n = tid + i * THREADS;
            int orig = (n & ~15) | ((n & 3) << 2) | ((n >> 2) & 3);
            rs[n] = rg[orig];
        }
    }
    __syncthreads();

    // ldmatrix lane address components (constant per thread)
    const int la_row = ((lane >> 3) & 1) * 8 + (lane & 7);   // A: row within 16
    const int la_k16 = (lane >> 4);                          // A: +16B for k+8
    const int lb_row = lane & 7;                             // B: n within 8
    const int lb_k16 = (lane >> 3);                          // B: granule 0..3
    const int m0 = wid * 32;

    // ================= persistent tile loop =================
    for (int tile = bid; tile < NTILES; tile += NCTA) {
        // ---- stage x tile: coalesced read + shfl xsq + swizzled store ----
        {
            const float4* xg = reinterpret_cast<const float4*>(x) + (size_t)tile * 2048;
#pragma unroll 4
            for (int i = 0; i < 16; i++) {
                int j = tid + i * THREADS;
                float4 v = xg[j];
                float p = v.x * v.x;
                p = fmaf(v.y, v.y, p);
                p = fmaf(v.z, v.z, p);
                p = fmaf(v.w, v.w, p);
                p += __shfl_xor_sync(0xffffffffu, p, 1);
                p += __shfl_xor_sync(0xffffffffu, p, 2);
                p += __shfl_xor_sync(0xffffffffu, p, 4);
                p += __shfl_xor_sync(0xffffffffu, p, 8);
                stage_f4(smemc, OFF_XHI, OFF_XLO, j >> 4, j & 15, v);
                if ((tid & 15) == 0) smf[OFF_XSQ / 4 + (j >> 4)] = p;
            }
        }
        __syncthreads();

        // ---- A fragments: 32 rows per warp = two 16-row groups ----
        uint32_t ah0[16], al0[16], ah1[16], al1[16];
#pragma unroll
        for (int s = 0; s < 4; s++) {
            int r0 = m0 + la_row;
            int r1 = r0 + 16;
            int kb = s * 32 + la_k16 * 16;
            ldsm4(ah0[4 * s], ah0[4 * s + 1], ah0[4 * s + 2], ah0[4 * s + 3],
                  swz(su + OFF_XHI, r0, kb));
            ldsm4(al0[4 * s], al0[4 * s + 1], al0[4 * s + 2], al0[4 * s + 3],
                  swz(su + OFF_XLO, r0, kb));
            ldsm4(ah1[4 * s], ah1[4 * s + 1], ah1[4 * s + 2], ah1[4 * s + 3],
                  swz(su + OFF_XHI, r1, kb));
            ldsm4(al1[4 * s], al1[4 * s + 1], al1[4 * s + 2], al1[4 * s + 3],
                  swz(su + OFF_XLO, r1, kb));
        }
        float xs0 = smf[OFF_XSQ / 4 + m0 + (lane >> 2)];
        float xs1 = smf[OFF_XSQ / 4 + m0 + (lane >> 2) + 8];
        float xs2 = smf[OFF_XSQ / 4 + m0 + (lane >> 2) + 16];
        float xs3 = smf[OFF_XSQ / 4 + m0 + (lane >> 2) + 24];

        float den0 = 0.f, den1 = 0.f, den2 = 0.f, den3 = 0.f;
        ull num0[4] = {0, 0, 0, 0};
        ull num1[4] = {0, 0, 0, 0};
        ull num2[4] = {0, 0, 0, 0};
        ull num3[4] = {0, 0, 0, 0};

        // ---- fetch B fragments + sk/rw for one n-block into registers ----
        auto ldB = [&](int nb, BFrag& F) {
            const int n0 = nb * 8;
#pragma unroll
            for (int p = 0; p < 2; p++) {
                int row = n0 + lb_row;
                int kb = p * 64 + lb_k16 * 16;
                ldsm4(F.bh[4 * p], F.bh[4 * p + 1], F.bh[4 * p + 2], F.bh[4 * p + 3],
                      swz(su + OFF_CHI, row, kb));
                ldsm4(F.bl[4 * p], F.bl[4 * p + 1], F.bl[4 * p + 2], F.bl[4 * p + 3],
                      swz(su + OFF_CLO, row, kb));
            }
            F.skv = *reinterpret_cast<const float4*>(
                smemc + OFF_SK + n0 * 8 + lq * 16);
            const ulonglong2* wp = reinterpret_cast<const ulonglong2*>(
                smemc + OFF_RW + nb * 256 + lq * 16);
            F.w0 = wp[0];
            F.w1 = wp[4];
            F.w2 = wp[8];
            F.w3 = wp[12];
        };

        // ---- consume one n-block: MMAs (g0 first, then g1), then epilogues ----
        auto body = [&](const BFrag& F) {
            float acc0[4] = {0.f, 0.f, 0.f, 0.f};
            float acc1[4] = {0.f, 0.f, 0.f, 0.f};
            // group 0: all 12 MMAs first so acc0 completes early
#pragma unroll
            for (int s = 0; s < 4; s++) {
                int bi = (s >> 1) * 4 + (s & 1) * 2;
                mma16816(acc0, &ah0[4 * s], F.bh[bi], F.bh[bi + 1]);
            }
#pragma unroll
            for (int s = 0; s < 4; s++) {
                int bi = (s >> 1) * 4 + (s & 1) * 2;
                mma16816(acc0, &ah0[4 * s], F.bl[bi], F.bl[bi + 1]);
            }
#pragma unroll
            for (int s = 0; s < 4; s++) {
                int bi = (s >> 1) * 4 + (s & 1) * 2;
                mma16816(acc0, &al0[4 * s], F.bh[bi], F.bh[bi + 1]);
            }
            // group 1: issued before epilogue(g0) so tensor pipe stays fed
#pragma unroll
            for (int s = 0; s < 4; s++) {
                int bi = (s >> 1) * 4 + (s & 1) * 2;
                mma16816(acc1, &ah1[4 * s], F.bh[bi], F.bh[bi + 1]);
            }
#pragma unroll
            for (int s = 0; s < 4; s++) {
                int bi = (s >> 1) * 4 + (s & 1) * 2;
                mma16816(acc1, &ah1[4 * s], F.bl[bi], F.bl[bi + 1]);
            }
#pragma unroll
            for (int s = 0; s < 4; s++) {
                int bi = (s >> 1) * 4 + (s & 1) * 2;
                mma16816(acc1, &al1[4 * s], F.bh[bi], F.bh[bi + 1]);
            }

            // epilogue g0 — overlaps g1's tensor execution
            {
                float m00 = ex2f(fmaf(F.skv.x, fmaf(acc0[0], 2.f, -xs0), F.skv.y));
                float m01 = ex2f(fmaf(F.skv.z, fmaf(acc0[1], 2.f, -xs0), F.skv.w));
                float m10 = ex2f(fmaf(F.skv.x, fmaf(acc0[2], 2.f, -xs1), F.skv.y));
                float m11 = ex2f(fmaf(F.skv.z, fmaf(acc0[3], 2.f, -xs1), F.skv.w));
                den0 += m00 + m01;
                den1 += m10 + m11;
                ull mA0 = pack2(m00), mB0 = pack2(m01);
                ull mA1 = pack2(m10), mB1 = pack2(m11);
                num0[0] = ffma2(mA0, F.w0.x, num0[0]);
                num0[1] = ffma2(mA0, F.w0.y, num0[1]);
                num0[2] = ffma2(mA0, F.w1.x, num0[2]);
                num0[3] = ffma2(mA0, F.w1.y, num0[3]);
                num0[0] = ffma2(mB0, F.w2.x, num0[0]);
                num0[1] = ffma2(mB0, F.w2.y, num0[1]);
                num0[2] = ffma2(mB0, F.w3.x, num0[2]);
                num0[3] = ffma2(mB0, F.w3.y, num0[3]);
                num1[0] = ffma2(mA1, F.w0.x, num1[0]);
                num1[1] = ffma2(mA1, F.w0.y, num1[1]);
                num1[2] = ffma2(mA1, F.w1.x, num1[2]);
                num1[3] = ffma2(mA1, F.w1.y, num1[3]);
                num1[0] = ffma2(mB1, F.w2.x, num1[0]);
                num1[1] = ffma2(mB1, F.w2.y, num1[1]);
                num1[2] = ffma2(mB1, F.w3.x, num1[2]);
                num1[3] = ffma2(mB1, F.w3.y, num1[3]);
            }
            // epilogue g1 — overlaps next iteration's LDSM + g0 MMAs
            {
                float m00 = ex2f(fmaf(F.skv.x, fmaf(acc1[0], 2.f, -xs2), F.skv.y));
                float m01 = ex2f(fmaf(F.skv.z, fmaf(acc1[1], 2.f, -xs2), F.skv.w));
                float m10 = ex2f(fmaf(F.skv.x, fmaf(acc1[2], 2.f, -xs3), F.skv.y));
                float m11 = ex2f(fmaf(F.skv.z, fmaf(acc1[3], 2.f, -xs3), F.skv.w));
                den2 += m00 + m01;
                den3 += m10 + m11;
                ull mA0 = pack2(m00), mB0 = pack2(m01);
                ull mA1 = pack2(m10), mB1 = pack2(m11);
                num2[0] = ffma2(mA0, F.w0.x, num2[0]);
                num2[1] = ffma2(mA0, F.w0.y, num2[1]);
                num2[2] = ffma2(mA0, F.w1.x, num2[2]);
                num2[3] = ffma2(mA0, F.w1.y, num2[3]);
                num2[0] = ffma2(mB0, F.w2.x, num2[0]);
                num2[1] = ffma2(mB0, F.w2.y, num2[1]);
                num2[2] = ffma2(mB0, F.w3.x, num2[2]);
                num2[3] = ffma2(mB0, F.w3.y, num2[3]);
                num3[0] = ffma2(mA1, F.w0.x, num3[0]);
                num3[1] = ffma2(mA1, F.w0.y, num3[1]);
                num3[2] = ffma2(mA1, F.w1.x, num3[2]);
                num3[3] = ffma2(mA1, F.w1.y, num3[3]);
                num3[0] = ffma2(mB1, F.w2.x, num3[0]);
                num3[1] = ffma2(mB1, F.w2.y, num3[1]);
                num3[2] = ffma2(mB1, F.w3.x, num3[2]);
                num3[3] = ffma2(mB1, F.w3.y, num3[3]);
            }
        };

        // ---- software-pipelined n-block loop (double-buffered B) ----
        {
            BFrag FA, FB;
            ldB(0, FA);
#pragma unroll 2
            for (int nb = 0; nb < 32; nb += 2) {
                ldB(nb + 1, FB);
                body(FA);
                if (nb + 2 < 32) ldB(nb + 2, FA);
                body(FB);
            }
        }

        // ---- quad reduction (lane bits 0..1) ----
#pragma unroll
        for (int s = 1; s < 4; s <<= 1) {
            den0 += __shfl_xor_sync(0xffffffffu, den0, s);
            den1 += __shfl_xor_sync(0xffffffffu, den1, s);
            den2 += __shfl_xor_sync(0xffffffffu, den2, s);
            den3 += __shfl_xor_sync(0xffffffffu, den3, s);
#pragma unroll
            for (int k = 0; k < 4; k++) {
                float2 u;
                u = unpack2(num0[k]);
                u.x += __shfl_xor_sync(0xffffffffu, u.x, s);
                u.y += __shfl_xor_sync(0xffffffffu, u.y, s);
                asm("mov.b64 %0, {%1, %2};" : "=l"(num0[k]) : "f"(u.x), "f"(u.y));
                u = unpack2(num1[k]);
                u.x += __shfl_xor_sync(0xffffffffu, u.x, s);
                u.y += __shfl_xor_sync(0xffffffffu, u.y, s);
                asm("mov.b64 %0, {%1, %2};" : "=l"(num1[k]) : "f"(u.x), "f"(u.y));
                u = unpack2(num2[k]);
                u.x += __shfl_xor_sync(0xffffffffu, u.x, s);
                u.y += __shfl_xor_sync(0xffffffffu, u.y, s);
                asm("mov.b64 %0, {%1, %2};" : "=l"(num2[k]) : "f"(u.x), "f"(u.y));
                u = unpack2(num3[k]);
                u.x += __shfl_xor_sync(0xffffffffu, u.x, s);
                u.y += __shfl_xor_sync(0xffffffffu, u.y, s);
                asm("mov.b64 %0, {%1, %2};" : "=l"(num3[k]) : "f"(u.x), "f"(u.y));
            }
        }

        if ((lane & 3) == 0) {
            size_t gr = (size_t)tile * 128 + m0 + (lane >> 2);
            float inv;
            float2 u;
            float4 o;
            float4* go;
#define WRITE_ROWS(numA, denA, roff)                                        \
            inv = 1.0f / (denA);                                            \
            go = reinterpret_cast<float4*>(out + (gr + (roff)) * O_N);      \
            u = unpack2(numA[0]); o.x = u.x * inv; o.y = u.y * inv;         \
            u = unpack2(numA[1]); o.z = u.x * inv; o.w = u.y * inv;         \
            go[0] = o;                                                      \
            u = unpack2(numA[2]); o.x = u.x * inv; o.y = u.y * inv;         \
            u = unpack2(numA[3]); o.z = u.x * inv; o.w = u.y * inv;         \
            go[1] = o;
            WRITE_ROWS(num0, den0, 0)
            WRITE_ROWS(num1, den1, 8)
            WRITE_ROWS(num2, den2, 16)
            WRITE_ROWS(num3, den3, 24)
#undef WRITE_ROWS
        }
        __syncthreads();   // protect x tile before next stage
    }
}

extern "C" void kernel_launch(void* const* d_in, const int* in_sizes, int n_in,
                              void* d_out, int out_size) {
    const float* x       = (const float*)d_in[0];
    const float* centers = (const float*)d_in[1];
    const float* widths  = (const float*)d_in[2];
    const float* rw      = (const float*)d_in[3];
    float* out = (float*)d_out;

    cudaFuncSetAttribute(fuzzy_mma,
                         cudaFuncAttributeMaxDynamicSharedMemorySize, SMEM_BYTES);
    fuzzy_mma<<<NCTA, THREADS, SMEM_BYTES>>>(x, centers, widths, rw, out);
}